// round 1
// baseline (speedup 1.0000x reference)
#include <cuda_runtime.h>
#include <math.h>

// Problem constants (fixed shapes for this problem)
#define NODES_MAX 100000
#define EDGES_MAX 3200000
#define D 256

// Scratch (device globals — no runtime allocation allowed)
__device__ float g_y[(size_t)NODES_MAX * D];   // aggregated features (pre-GEMM), 102.4 MB
__device__ int   g_colidx[EDGES_MAX];          // CSR column indices
__device__ int   g_deg[NODES_MAX];
__device__ int   g_pos[NODES_MAX];
__device__ int   g_rowptr[NODES_MAX + 1];
__device__ float g_norm[NODES_MAX];
__device__ float g_bcoef[NODES_MAX];

// ---------------------------------------------------------------- CSR build
__global__ void k_zero(int n) {
    int i = blockIdx.x * blockDim.x + threadIdx.x;
    if (i < n) g_deg[i] = 0;
}

__global__ void k_hist(const int* __restrict__ rows, int E) {
    int i = blockIdx.x * blockDim.x + threadIdx.x;
    if (i < E) atomicAdd(&g_deg[rows[i]], 1);
}

// Single-block exclusive scan over degrees; also emits rowptr, pos, norm.
__global__ void k_scan(int n) {
    __shared__ int sh[1024];
    int t = threadIdx.x;
    int chunk = (n + 1023) / 1024;
    int beg = t * chunk;
    int end = min(n, beg + chunk);
    int sum = 0;
    for (int i = beg; i < end; i++) sum += g_deg[i];
    sh[t] = sum;
    __syncthreads();
    for (int off = 1; off < 1024; off <<= 1) {
        int v = (t >= off) ? sh[t - off] : 0;
        __syncthreads();
        sh[t] += v;
        __syncthreads();
    }
    int run = sh[t] - sum;  // exclusive prefix
    for (int i = beg; i < end; i++) {
        int d = g_deg[i];
        g_rowptr[i] = run;
        g_pos[i]    = run;
        g_norm[i]   = rsqrtf(1.0f + (float)d);
        run += d;
    }
    if (beg < n && end == n) g_rowptr[n] = run;
}

__global__ void k_scatter(const int* __restrict__ rows, const int* __restrict__ cols, int E) {
    int i = blockIdx.x * blockDim.x + threadIdx.x;
    if (i < E) {
        int r = rows[i];
        int p = atomicAdd(&g_pos[r], 1);
        g_colidx[p] = cols[i];
    }
}

// ------------------------------------------------- per-node gather-reduce
// One warp per node. y_i = norm_i * sum_{j in N(i)} norm_j x_j + norm_i^2 x_i
// bcoef_i = norm_i * (sum_j norm_j + norm_i)     (bias coefficient)
__global__ void k_aggregate(const float* __restrict__ x, int n) {
    int gw   = (blockIdx.x * blockDim.x + threadIdx.x) >> 5;
    int lane = threadIdx.x & 31;
    if (gw >= n) return;
    int i   = gw;
    int beg = g_rowptr[i];
    int end = g_rowptr[i + 1];

    float4 a0 = make_float4(0.f, 0.f, 0.f, 0.f);
    float4 a1 = make_float4(0.f, 0.f, 0.f, 0.f);
    float  s  = 0.f;

    for (int j = beg; j < end; j++) {
        int   c  = __ldg(&g_colidx[j]);
        float nc = __ldg(&g_norm[c]);
        s += nc;
        const float4* xr = (const float4*)(x + (size_t)c * D);
        float4 v0 = __ldg(&xr[lane]);
        float4 v1 = __ldg(&xr[lane + 32]);
        a0.x = fmaf(nc, v0.x, a0.x);  a0.y = fmaf(nc, v0.y, a0.y);
        a0.z = fmaf(nc, v0.z, a0.z);  a0.w = fmaf(nc, v0.w, a0.w);
        a1.x = fmaf(nc, v1.x, a1.x);  a1.y = fmaf(nc, v1.y, a1.y);
        a1.z = fmaf(nc, v1.z, a1.z);  a1.w = fmaf(nc, v1.w, a1.w);
    }

    float ni = g_norm[i];
    float c2 = ni * ni;
    const float4* xi = (const float4*)(x + (size_t)i * D);
    float4 s0 = __ldg(&xi[lane]);
    float4 s1 = __ldg(&xi[lane + 32]);

    float4 y0, y1;
    y0.x = fmaf(ni, a0.x, c2 * s0.x);  y0.y = fmaf(ni, a0.y, c2 * s0.y);
    y0.z = fmaf(ni, a0.z, c2 * s0.z);  y0.w = fmaf(ni, a0.w, c2 * s0.w);
    y1.x = fmaf(ni, a1.x, c2 * s1.x);  y1.y = fmaf(ni, a1.y, c2 * s1.y);
    y1.z = fmaf(ni, a1.z, c2 * s1.z);  y1.w = fmaf(ni, a1.w, c2 * s1.w);

    float4* yr = (float4*)(g_y + (size_t)i * D);
    yr[lane]      = y0;
    yr[lane + 32] = y1;
    if (lane == 0) g_bcoef[i] = ni * (s + ni);
}

// ------------------------------------------------------------------ GEMM
// out[m][n] = sum_k y[m][k] * W[n][k] + bcoef[m] * bias[n]
// Classic SGEMM tiling: 128x128 block tile, BK=16, 256 threads, 8x8 microtile.
#define BM 128
#define BN 128
#define BK 16

__global__ __launch_bounds__(256) void k_gemm(const float* __restrict__ Wm,
                                              const float* __restrict__ bias,
                                              float* __restrict__ out, int M) {
    __shared__ float As[BK][BM + 4];
    __shared__ float Bs[BK][BN + 4];
    int tid = threadIdx.x;
    int bm = blockIdx.x * BM;
    int bn = blockIdx.y * BN;
    int tx = tid & 15;   // 16 column groups
    int ty = tid >> 4;   // 16 row groups

    float acc[8][8];
#pragma unroll
    for (int i = 0; i < 8; i++)
#pragma unroll
        for (int j = 0; j < 8; j++) acc[i][j] = 0.f;

    for (int k0 = 0; k0 < D; k0 += BK) {
#pragma unroll
        for (int l = 0; l < 2; l++) {
            int v   = tid + l * 256;
            int row = v >> 2;
            int kq  = (v & 3) << 2;
            int m   = bm + row;
            float4 a = (m < M) ? *(const float4*)(g_y + (size_t)m * D + k0 + kq)
                               : make_float4(0.f, 0.f, 0.f, 0.f);
            As[kq + 0][row] = a.x; As[kq + 1][row] = a.y;
            As[kq + 2][row] = a.z; As[kq + 3][row] = a.w;
            float4 b = *(const float4*)(Wm + (size_t)(bn + row) * D + k0 + kq);
            Bs[kq + 0][row] = b.x; Bs[kq + 1][row] = b.y;
            Bs[kq + 2][row] = b.z; Bs[kq + 3][row] = b.w;
        }
        __syncthreads();
#pragma unroll
        for (int k = 0; k < BK; k++) {
            float4 a0 = *(const float4*)&As[k][ty * 8];
            float4 a1 = *(const float4*)&As[k][ty * 8 + 4];
            float4 b0 = *(const float4*)&Bs[k][tx * 8];
            float4 b1 = *(const float4*)&Bs[k][tx * 8 + 4];
            float a[8] = {a0.x, a0.y, a0.z, a0.w, a1.x, a1.y, a1.z, a1.w};
            float b[8] = {b0.x, b0.y, b0.z, b0.w, b1.x, b1.y, b1.z, b1.w};
#pragma unroll
            for (int i = 0; i < 8; i++)
#pragma unroll
                for (int j = 0; j < 8; j++)
                    acc[i][j] = fmaf(a[i], b[j], acc[i][j]);
        }
        __syncthreads();
    }

    float bl[8];
#pragma unroll
    for (int j = 0; j < 8; j++) bl[j] = __ldg(&bias[bn + tx * 8 + j]);

#pragma unroll
    for (int i = 0; i < 8; i++) {
        int m = bm + ty * 8 + i;
        if (m < M) {
            float bc = g_bcoef[m];
            float4 o0, o1;
            o0.x = fmaf(bc, bl[0], acc[i][0]); o0.y = fmaf(bc, bl[1], acc[i][1]);
            o0.z = fmaf(bc, bl[2], acc[i][2]); o0.w = fmaf(bc, bl[3], acc[i][3]);
            o1.x = fmaf(bc, bl[4], acc[i][4]); o1.y = fmaf(bc, bl[5], acc[i][5]);
            o1.z = fmaf(bc, bl[6], acc[i][6]); o1.w = fmaf(bc, bl[7], acc[i][7]);
            float4* op = (float4*)(out + (size_t)m * D + bn + tx * 8);
            op[0] = o0;
            op[1] = o1;
        }
    }
}

// ------------------------------------------------------------- entry point
extern "C" void kernel_launch(void* const* d_in, const int* in_sizes, int n_in,
                              void* d_out, int out_size) {
    const float* x    = (const float*)d_in[0];
    const float* W    = (const float*)d_in[1];
    const float* bias = (const float*)d_in[2];
    const int*   rows = (const int*)d_in[3];
    const int*   cols = (const int*)d_in[4];
    int N = in_sizes[0] / D;
    int E = in_sizes[3];
    if (N > NODES_MAX) N = NODES_MAX;
    if (E > EDGES_MAX) E = EDGES_MAX;

    k_zero<<<(N + 255) / 256, 256>>>(N);
    k_hist<<<(E + 255) / 256, 256>>>(rows, E);
    k_scan<<<1, 1024>>>(N);
    k_scatter<<<(E + 255) / 256, 256>>>(rows, cols, E);
    k_aggregate<<<(N * 32 + 255) / 256, 256>>>(x, N);
    dim3 grid((N + BM - 1) / BM, D / BN);
    k_gemm<<<grid, 256>>>(W, bias, (float*)d_out, N);
}

// round 3
// speedup vs baseline: 1.1153x; 1.1153x over previous
#include <cuda_runtime.h>
#include <cuda_bf16.h>
#include <mma.h>
#include <math.h>
#include <cstdint>

using namespace nvcuda;

// Problem constants
#define NODES_MAX 100000
#define EDGES_MAX 3200000
#define D 256
#define NPAD 100224           // 783*128 padded M

// ---------------- scratch (device globals; no runtime allocation) ----------
__device__ __nv_bfloat16 g_yhi[(size_t)NPAD * D];
__device__ __nv_bfloat16 g_ylo[(size_t)NPAD * D];
__device__ __nv_bfloat16 g_Whi[D * D];
__device__ __nv_bfloat16 g_Wlo[D * D];
__device__ int   g_colidx[EDGES_MAX];
__device__ int   g_deg[NODES_MAX];
__device__ int   g_pos[NODES_MAX];
__device__ int   g_rowptr[NODES_MAX + 1];
__device__ float g_norm[NODES_MAX];
__device__ float g_bcoef[NODES_MAX];

// ---------------- helpers --------------------------------------------------
__device__ __forceinline__ uint32_t smem_u32(const void* p) {
    uint32_t a;
    asm("{ .reg .u64 t; cvta.to.shared.u64 t, %1; cvt.u32.u64 %0, t; }" : "=r"(a) : "l"(p));
    return a;
}
__device__ __forceinline__ void cp16(void* dst, const void* src) {
    uint32_t d = smem_u32(dst);
    asm volatile("cp.async.cg.shared.global [%0], [%1], 16;" :: "r"(d), "l"(src) : "memory");
}
#define CP_COMMIT() asm volatile("cp.async.commit_group;" ::: "memory")
#define CP_WAIT(n)  asm volatile("cp.async.wait_group %0;" :: "n"(n) : "memory")

// ---------------------------------------------------------------- CSR build
__global__ void k_zero(int n) {
    int i = blockIdx.x * blockDim.x + threadIdx.x;
    if (i < n) g_deg[i] = 0;
}
__global__ void k_hist(const int* __restrict__ rows, int E) {
    int i = blockIdx.x * blockDim.x + threadIdx.x;
    if (i < E) atomicAdd(&g_deg[rows[i]], 1);
}
__global__ void k_scan(int n) {
    __shared__ int sh[1024];
    int t = threadIdx.x;
    int chunk = (n + 1023) / 1024;
    int beg = t * chunk, end = min(n, beg + chunk);
    int sum = 0;
    for (int i = beg; i < end; i++) sum += g_deg[i];
    sh[t] = sum;
    __syncthreads();
    for (int off = 1; off < 1024; off <<= 1) {
        int v = (t >= off) ? sh[t - off] : 0;
        __syncthreads();
        sh[t] += v;
        __syncthreads();
    }
    int run = sh[t] - sum;
    for (int i = beg; i < end; i++) {
        int d = g_deg[i];
        g_rowptr[i] = run;
        g_pos[i]    = run;
        g_norm[i]   = rsqrtf(1.0f + (float)d);
        run += d;
    }
    if (beg < n && end == n) g_rowptr[n] = run;
}
__global__ void k_scatter(const int* __restrict__ rows, const int* __restrict__ cols, int E) {
    int i = blockIdx.x * blockDim.x + threadIdx.x;
    if (i < E) {
        int r = rows[i];
        int p = atomicAdd(&g_pos[r], 1);
        g_colidx[p] = cols[i];
    }
}

// ---------------- W split into bf16 hi/lo ----------------------------------
__global__ void k_wsplit(const float* __restrict__ W) {
    int i = blockIdx.x * blockDim.x + threadIdx.x;
    if (i < D * D) {
        float v = W[i];
        __nv_bfloat16 h = __float2bfloat16(v);
        g_Whi[i] = h;
        g_Wlo[i] = __float2bfloat16(v - __bfloat162float(h));
    }
}

// ---------------- per-node gather-reduce, emit bf16 hi/lo ------------------
__device__ __forceinline__ void split_store4(__nv_bfloat16* hp, __nv_bfloat16* lp, float4 v) {
    __nv_bfloat16 h0 = __float2bfloat16(v.x), h1 = __float2bfloat16(v.y);
    __nv_bfloat16 h2 = __float2bfloat16(v.z), h3 = __float2bfloat16(v.w);
    __nv_bfloat16 l0 = __float2bfloat16(v.x - __bfloat162float(h0));
    __nv_bfloat16 l1 = __float2bfloat16(v.y - __bfloat162float(h1));
    __nv_bfloat16 l2 = __float2bfloat16(v.z - __bfloat162float(h2));
    __nv_bfloat16 l3 = __float2bfloat16(v.w - __bfloat162float(h3));
    uint2 hu, lu;
    hu.x = ((uint32_t)__bfloat16_as_ushort(h1) << 16) | __bfloat16_as_ushort(h0);
    hu.y = ((uint32_t)__bfloat16_as_ushort(h3) << 16) | __bfloat16_as_ushort(h2);
    lu.x = ((uint32_t)__bfloat16_as_ushort(l1) << 16) | __bfloat16_as_ushort(l0);
    lu.y = ((uint32_t)__bfloat16_as_ushort(l3) << 16) | __bfloat16_as_ushort(l2);
    *(uint2*)hp = hu;
    *(uint2*)lp = lu;
}

__global__ void k_aggregate(const float* __restrict__ x, int n) {
    int gw   = (blockIdx.x * blockDim.x + threadIdx.x) >> 5;
    int lane = threadIdx.x & 31;
    if (gw >= n) return;
    int i   = gw;
    int beg = g_rowptr[i];
    int end = g_rowptr[i + 1];

    float4 a0 = make_float4(0.f, 0.f, 0.f, 0.f);
    float4 a1 = make_float4(0.f, 0.f, 0.f, 0.f);
    float  s  = 0.f;

    int j = beg;
    for (; j + 1 < end; j += 2) {
        int   c0 = __ldg(&g_colidx[j]);
        int   c1 = __ldg(&g_colidx[j + 1]);
        float n0 = __ldg(&g_norm[c0]);
        float n1 = __ldg(&g_norm[c1]);
        const float4* xr0 = (const float4*)(x + (size_t)c0 * D);
        const float4* xr1 = (const float4*)(x + (size_t)c1 * D);
        float4 u0 = __ldg(&xr0[lane]);
        float4 u1 = __ldg(&xr0[lane + 32]);
        float4 v0 = __ldg(&xr1[lane]);
        float4 v1 = __ldg(&xr1[lane + 32]);
        s += n0 + n1;
        a0.x = fmaf(n0, u0.x, a0.x); a0.y = fmaf(n0, u0.y, a0.y);
        a0.z = fmaf(n0, u0.z, a0.z); a0.w = fmaf(n0, u0.w, a0.w);
        a1.x = fmaf(n0, u1.x, a1.x); a1.y = fmaf(n0, u1.y, a1.y);
        a1.z = fmaf(n0, u1.z, a1.z); a1.w = fmaf(n0, u1.w, a1.w);
        a0.x = fmaf(n1, v0.x, a0.x); a0.y = fmaf(n1, v0.y, a0.y);
        a0.z = fmaf(n1, v0.z, a0.z); a0.w = fmaf(n1, v0.w, a0.w);
        a1.x = fmaf(n1, v1.x, a1.x); a1.y = fmaf(n1, v1.y, a1.y);
        a1.z = fmaf(n1, v1.z, a1.z); a1.w = fmaf(n1, v1.w, a1.w);
    }
    if (j < end) {
        int   c  = __ldg(&g_colidx[j]);
        float nc = __ldg(&g_norm[c]);
        s += nc;
        const float4* xr = (const float4*)(x + (size_t)c * D);
        float4 v0 = __ldg(&xr[lane]);
        float4 v1 = __ldg(&xr[lane + 32]);
        a0.x = fmaf(nc, v0.x, a0.x); a0.y = fmaf(nc, v0.y, a0.y);
        a0.z = fmaf(nc, v0.z, a0.z); a0.w = fmaf(nc, v0.w, a0.w);
        a1.x = fmaf(nc, v1.x, a1.x); a1.y = fmaf(nc, v1.y, a1.y);
        a1.z = fmaf(nc, v1.z, a1.z); a1.w = fmaf(nc, v1.w, a1.w);
    }

    float ni = g_norm[i];
    float c2 = ni * ni;
    const float4* xi = (const float4*)(x + (size_t)i * D);
    float4 s0 = __ldg(&xi[lane]);
    float4 s1 = __ldg(&xi[lane + 32]);

    float4 y0, y1;
    y0.x = fmaf(ni, a0.x, c2 * s0.x); y0.y = fmaf(ni, a0.y, c2 * s0.y);
    y0.z = fmaf(ni, a0.z, c2 * s0.z); y0.w = fmaf(ni, a0.w, c2 * s0.w);
    y1.x = fmaf(ni, a1.x, c2 * s1.x); y1.y = fmaf(ni, a1.y, c2 * s1.y);
    y1.z = fmaf(ni, a1.z, c2 * s1.z); y1.w = fmaf(ni, a1.w, c2 * s1.w);

    size_t base = (size_t)i * D + 4 * lane;
    split_store4(g_yhi + base,       g_ylo + base,       y0);
    split_store4(g_yhi + base + 128, g_ylo + base + 128, y1);
    if (lane == 0) g_bcoef[i] = ni * (s + ni);
}

// ---------------- WMMA GEMM ------------------------------------------------
// out[m][n] = sum_k y[m][k]*W[n][k] + bcoef[m]*bias[n]
// bf16 3-split: virtual K' = 768 = [yhi*Whi | yhi*Wlo | ylo*Whi], fp32 acc.
// Block tile 128x128, 8 warps (4 along M x 2 along N), warp tile 32x64.
// BK = 32 bf16 per stage, 24 stages, 2-stage cp.async double buffer.
#define GBM 128
#define GBN 128
#define GBK 32
#define NSTAGE 24
#define TS 40                       // smem tile row stride in bf16 (80B, 16B-aligned rows)
#define TILE_BYTES (128 * TS * 2)   // 10240
#define STG_LD 132                  // epilogue staging row stride (f32)
#define SMEM_BIAS 0
#define SMEM_TILES 512
#define GEMM_SMEM (512 + 128 * STG_LD * 4)   // 512 + 67584 = 68096 (tiles union staging)

__global__ __launch_bounds__(256, 2) void k_gemm_wmma(const float* __restrict__ bias,
                                                      float* __restrict__ out, int M) {
    extern __shared__ char sm[];
    float* s_bias = (float*)(sm + SMEM_BIAS);
    char*  tiles  = sm + SMEM_TILES;
    __nv_bfloat16* Abuf[2] = {(__nv_bfloat16*)(tiles),
                              (__nv_bfloat16*)(tiles + 2 * TILE_BYTES)};
    __nv_bfloat16* Bbuf[2] = {(__nv_bfloat16*)(tiles + TILE_BYTES),
                              (__nv_bfloat16*)(tiles + 3 * TILE_BYTES)};
    float* stg = (float*)tiles;

    int tid = threadIdx.x;
    int wid = tid >> 5;
    int wm  = wid & 3;          // 4 warps along M
    int wn  = wid >> 2;         // 2 warps along N
    int bm  = blockIdx.x * GBM;
    int bn  = blockIdx.y * GBN;

    if (tid < 128) s_bias[tid] = bias[bn + tid];

    wmma::fragment<wmma::accumulator, 16, 16, 16, float> acc[2][4];
#pragma unroll
    for (int i = 0; i < 2; i++)
#pragma unroll
        for (int jj = 0; jj < 4; jj++) wmma::fill_fragment(acc[i][jj], 0.f);

    // stage c: seg = c/8 in {(yhi,Whi),(yhi,Wlo),(ylo,Whi)}, kk = (c%8)*32
    auto issue = [&](int c) {
        int seg = c >> 3;
        int kk  = (c & 7) * GBK;
        const __nv_bfloat16* Asrc = (seg == 2) ? g_ylo : g_yhi;
        const __nv_bfloat16* Bsrc = (seg == 1) ? g_Wlo : g_Whi;
        __nv_bfloat16* Ad = Abuf[c & 1];
        __nv_bfloat16* Bd = Bbuf[c & 1];
#pragma unroll
        for (int r = 0; r < 2; r++) {
            int u   = tid + r * 256;        // 512 16B-chunks per tile
            int row = u >> 2;
            int c8  = (u & 3) * 8;
            cp16(Ad + row * TS + c8, Asrc + (size_t)(bm + row) * D + kk + c8);
            cp16(Bd + row * TS + c8, Bsrc + (size_t)(bn + row) * D + kk + c8);
        }
    };

    issue(0);
    CP_COMMIT();
    for (int c = 0; c < NSTAGE; c++) {
        if (c + 1 < NSTAGE) { issue(c + 1); CP_COMMIT(); CP_WAIT(1); }
        else                { CP_WAIT(0); }
        __syncthreads();

        const __nv_bfloat16* As = Abuf[c & 1];
        const __nv_bfloat16* Bs = Bbuf[c & 1];
#pragma unroll
        for (int ks = 0; ks < GBK; ks += 16) {
            wmma::fragment<wmma::matrix_a, 16, 16, 16, __nv_bfloat16, wmma::row_major> af[2];
            wmma::fragment<wmma::matrix_b, 16, 16, 16, __nv_bfloat16, wmma::col_major> bf[4];
#pragma unroll
            for (int i = 0; i < 2; i++)
                wmma::load_matrix_sync(af[i], As + (wm * 32 + i * 16) * TS + ks, TS);
#pragma unroll
            for (int jj = 0; jj < 4; jj++)
                wmma::load_matrix_sync(bf[jj], Bs + (wn * 64 + jj * 16) * TS + ks, TS);
#pragma unroll
            for (int i = 0; i < 2; i++)
#pragma unroll
                for (int jj = 0; jj < 4; jj++)
                    wmma::mma_sync(acc[i][jj], af[i], bf[jj], acc[i][jj]);
        }
        __syncthreads();
    }

    // epilogue: stage accumulators to smem, fuse bcoef*bias, write out
#pragma unroll
    for (int i = 0; i < 2; i++)
#pragma unroll
        for (int jj = 0; jj < 4; jj++)
            wmma::store_matrix_sync(stg + (size_t)(wm * 32 + i * 16) * STG_LD + wn * 64 + jj * 16,
                                    acc[i][jj], STG_LD, wmma::mem_row_major);
    __syncthreads();

    int row  = tid >> 1;
    int half = tid & 1;
    int m    = bm + row;
    if (m < M) {
        float bc = g_bcoef[m];
        const float* sr = stg + (size_t)row * STG_LD + half * 64;
        float*       op = out + (size_t)m * D + bn + half * 64;
        const float* bl = s_bias + half * 64;
#pragma unroll
        for (int q = 0; q < 16; q++) {
            float4 v;
            v.x = sr[4 * q + 0] + bc * bl[4 * q + 0];
            v.y = sr[4 * q + 1] + bc * bl[4 * q + 1];
            v.z = sr[4 * q + 2] + bc * bl[4 * q + 2];
            v.w = sr[4 * q + 3] + bc * bl[4 * q + 3];
            *(float4*)(op + 4 * q) = v;
        }
    }
}

// ------------------------------------------------------------- entry point
extern "C" void kernel_launch(void* const* d_in, const int* in_sizes, int n_in,
                              void* d_out, int out_size) {
    const float* x    = (const float*)d_in[0];
    const float* W    = (const float*)d_in[1];
    const float* bias = (const float*)d_in[2];
    const int*   rows = (const int*)d_in[3];
    const int*   cols = (const int*)d_in[4];
    int N = in_sizes[0] / D;
    int E = in_sizes[3];
    if (N > NODES_MAX) N = NODES_MAX;
    if (E > EDGES_MAX) E = EDGES_MAX;

    cudaFuncSetAttribute(k_gemm_wmma, cudaFuncAttributeMaxDynamicSharedMemorySize, GEMM_SMEM);

    k_zero<<<(N + 255) / 256, 256>>>(N);
    k_hist<<<(E + 255) / 256, 256>>>(rows, E);
    k_wsplit<<<(D * D + 255) / 256, 256>>>(W);
    k_scan<<<1, 1024>>>(N);
    k_scatter<<<(E + 255) / 256, 256>>>(rows, cols, E);
    k_aggregate<<<(N * 32 + 255) / 256, 256>>>(x, N);
    dim3 grid((N + GBM - 1) / GBM, D / GBN);
    k_gemm_wmma<<<grid, 256, GEMM_SMEM>>>(bias, (float*)d_out, N);
}

// round 4
// speedup vs baseline: 1.5587x; 1.3976x over previous
#include <cuda_runtime.h>
#include <cuda_bf16.h>
#include <mma.h>
#include <math.h>
#include <cstdint>

using namespace nvcuda;

// Problem constants
#define NODES_MAX 100000
#define EDGES_MAX 3200000
#define D 256
#define NPAD 100224           // 783*128 padded M
#define SCAN_B 98             // scan blocks: 98*1024 >= 100000

// ---------------- scratch (device globals; no runtime allocation) ----------
__device__ __nv_bfloat16 g_yhi[(size_t)NPAD * D];
__device__ __nv_bfloat16 g_ylo[(size_t)NPAD * D];
__device__ __nv_bfloat16 g_Whi[D * D];
__device__ __nv_bfloat16 g_Wlo[D * D];
__device__ int   g_colidx[EDGES_MAX];
__device__ int   g_deg[NODES_MAX];
__device__ int   g_pos[NODES_MAX];
__device__ int   g_rowptr[NODES_MAX + 1];
__device__ float g_norm[NODES_MAX];
__device__ float g_bcoef[NODES_MAX];
__device__ int   g_part[SCAN_B];
__device__ int   g_partscan[SCAN_B];

// ---------------- helpers --------------------------------------------------
__device__ __forceinline__ uint32_t smem_u32(const void* p) {
    uint32_t a;
    asm("{ .reg .u64 t; cvta.to.shared.u64 t, %1; cvt.u32.u64 %0, t; }" : "=r"(a) : "l"(p));
    return a;
}
__device__ __forceinline__ void cp16(void* dst, const void* src) {
    uint32_t d = smem_u32(dst);
    asm volatile("cp.async.cg.shared.global [%0], [%1], 16;" :: "r"(d), "l"(src) : "memory");
}
#define CP_COMMIT() asm volatile("cp.async.commit_group;" ::: "memory")
#define CP_WAIT(n)  asm volatile("cp.async.wait_group %0;" :: "n"(n) : "memory")

// ---------------------------------------------------------------- CSR build
__global__ void k_zero(int n) {
    int i = blockIdx.x * blockDim.x + threadIdx.x;
    if (i < n) g_deg[i] = 0;
}
__global__ void k_hist(const int* __restrict__ rows, int E) {
    int i = blockIdx.x * blockDim.x + threadIdx.x;
    if (i < E) atomicAdd(&g_deg[rows[i]], 1);
}

// Phase 1: per-block degree sums
__global__ __launch_bounds__(1024) void k_part(int n) {
    __shared__ int wsum[32];
    int i = blockIdx.x * 1024 + threadIdx.x;
    int v = (i < n) ? g_deg[i] : 0;
    int s = v;
#pragma unroll
    for (int o = 16; o > 0; o >>= 1) s += __shfl_down_sync(0xffffffffu, s, o);
    if ((threadIdx.x & 31) == 0) wsum[threadIdx.x >> 5] = s;
    __syncthreads();
    if (threadIdx.x < 32) {
        int t = wsum[threadIdx.x];
#pragma unroll
        for (int o = 16; o > 0; o >>= 1) t += __shfl_down_sync(0xffffffffu, t, o);
        if (threadIdx.x == 0) g_part[blockIdx.x] = t;
    }
}

// Phase 2: exclusive scan of SCAN_B partials (single warp, shuffle scan)
__global__ void k_top() {
    int lane = threadIdx.x;
    int run = 0;
    for (int base = 0; base < SCAN_B; base += 32) {
        int idx = base + lane;
        int v = (idx < SCAN_B) ? g_part[idx] : 0;
        int x = v;
#pragma unroll
        for (int o = 1; o < 32; o <<= 1) {
            int y = __shfl_up_sync(0xffffffffu, x, o);
            if (lane >= o) x += y;
        }
        if (idx < SCAN_B) g_partscan[idx] = run + x - v;   // exclusive
        run += __shfl_sync(0xffffffffu, x, 31);
    }
}

// Phase 3: per-block exclusive scan + offset; write rowptr/pos/norm
__global__ __launch_bounds__(1024) void k_down(int n) {
    __shared__ int sh[1024];
    int t = threadIdx.x;
    int i = blockIdx.x * 1024 + t;
    int d = (i < n) ? g_deg[i] : 0;
    sh[t] = d;
    __syncthreads();
#pragma unroll
    for (int o = 1; o < 1024; o <<= 1) {
        int v = (t >= o) ? sh[t - o] : 0;
        __syncthreads();
        sh[t] += v;
        __syncthreads();
    }
    int excl = sh[t] - d + g_partscan[blockIdx.x];
    if (i < n) {
        g_rowptr[i] = excl;
        g_pos[i]    = excl;
        g_norm[i]   = rsqrtf(1.0f + (float)d);
        if (i == n - 1) g_rowptr[n] = excl + d;
    }
}

__global__ void k_scatter(const int* __restrict__ rows, const int* __restrict__ cols, int E) {
    int i = blockIdx.x * blockDim.x + threadIdx.x;
    if (i < E) {
        int r = rows[i];
        int p = atomicAdd(&g_pos[r], 1);
        g_colidx[p] = cols[i];
    }
}

// ---------------- W split into bf16 hi/lo ----------------------------------
__global__ void k_wsplit(const float* __restrict__ W) {
    int i = blockIdx.x * blockDim.x + threadIdx.x;
    if (i < D * D) {
        float v = W[i];
        __nv_bfloat16 h = __float2bfloat16(v);
        g_Whi[i] = h;
        g_Wlo[i] = __float2bfloat16(v - __bfloat162float(h));
    }
}

// ---------------- per-node gather-reduce, emit bf16 hi/lo ------------------
__device__ __forceinline__ void split_store4(__nv_bfloat16* hp, __nv_bfloat16* lp, float4 v) {
    __nv_bfloat16 h0 = __float2bfloat16(v.x), h1 = __float2bfloat16(v.y);
    __nv_bfloat16 h2 = __float2bfloat16(v.z), h3 = __float2bfloat16(v.w);
    __nv_bfloat16 l0 = __float2bfloat16(v.x - __bfloat162float(h0));
    __nv_bfloat16 l1 = __float2bfloat16(v.y - __bfloat162float(h1));
    __nv_bfloat16 l2 = __float2bfloat16(v.z - __bfloat162float(h2));
    __nv_bfloat16 l3 = __float2bfloat16(v.w - __bfloat162float(h3));
    uint2 hu, lu;
    hu.x = ((uint32_t)__bfloat16_as_ushort(h1) << 16) | __bfloat16_as_ushort(h0);
    hu.y = ((uint32_t)__bfloat16_as_ushort(h3) << 16) | __bfloat16_as_ushort(h2);
    lu.x = ((uint32_t)__bfloat16_as_ushort(l1) << 16) | __bfloat16_as_ushort(l0);
    lu.y = ((uint32_t)__bfloat16_as_ushort(l3) << 16) | __bfloat16_as_ushort(l2);
    *(uint2*)hp = hu;
    *(uint2*)lp = lu;
}

__global__ void k_aggregate(const float* __restrict__ x, int n) {
    int gw   = (blockIdx.x * blockDim.x + threadIdx.x) >> 5;
    int lane = threadIdx.x & 31;
    if (gw >= n) return;
    int i   = gw;
    int beg = g_rowptr[i];
    int end = g_rowptr[i + 1];

    float4 a0 = make_float4(0.f, 0.f, 0.f, 0.f);
    float4 a1 = make_float4(0.f, 0.f, 0.f, 0.f);
    float  s  = 0.f;

    int j = beg;
    for (; j + 1 < end; j += 2) {
        int   c0 = __ldg(&g_colidx[j]);
        int   c1 = __ldg(&g_colidx[j + 1]);
        float n0 = __ldg(&g_norm[c0]);
        float n1 = __ldg(&g_norm[c1]);
        const float4* xr0 = (const float4*)(x + (size_t)c0 * D);
        const float4* xr1 = (const float4*)(x + (size_t)c1 * D);
        float4 u0 = __ldg(&xr0[lane]);
        float4 u1 = __ldg(&xr0[lane + 32]);
        float4 v0 = __ldg(&xr1[lane]);
        float4 v1 = __ldg(&xr1[lane + 32]);
        s += n0 + n1;
        a0.x = fmaf(n0, u0.x, a0.x); a0.y = fmaf(n0, u0.y, a0.y);
        a0.z = fmaf(n0, u0.z, a0.z); a0.w = fmaf(n0, u0.w, a0.w);
        a1.x = fmaf(n0, u1.x, a1.x); a1.y = fmaf(n0, u1.y, a1.y);
        a1.z = fmaf(n0, u1.z, a1.z); a1.w = fmaf(n0, u1.w, a1.w);
        a0.x = fmaf(n1, v0.x, a0.x); a0.y = fmaf(n1, v0.y, a0.y);
        a0.z = fmaf(n1, v0.z, a0.z); a0.w = fmaf(n1, v0.w, a0.w);
        a1.x = fmaf(n1, v1.x, a1.x); a1.y = fmaf(n1, v1.y, a1.y);
        a1.z = fmaf(n1, v1.z, a1.z); a1.w = fmaf(n1, v1.w, a1.w);
    }
    if (j < end) {
        int   c  = __ldg(&g_colidx[j]);
        float nc = __ldg(&g_norm[c]);
        s += nc;
        const float4* xr = (const float4*)(x + (size_t)c * D);
        float4 v0 = __ldg(&xr[lane]);
        float4 v1 = __ldg(&xr[lane + 32]);
        a0.x = fmaf(nc, v0.x, a0.x); a0.y = fmaf(nc, v0.y, a0.y);
        a0.z = fmaf(nc, v0.z, a0.z); a0.w = fmaf(nc, v0.w, a0.w);
        a1.x = fmaf(nc, v1.x, a1.x); a1.y = fmaf(nc, v1.y, a1.y);
        a1.z = fmaf(nc, v1.z, a1.z); a1.w = fmaf(nc, v1.w, a1.w);
    }

    float ni = g_norm[i];
    float c2 = ni * ni;
    const float4* xi = (const float4*)(x + (size_t)i * D);
    float4 s0 = __ldg(&xi[lane]);
    float4 s1 = __ldg(&xi[lane + 32]);

    float4 y0, y1;
    y0.x = fmaf(ni, a0.x, c2 * s0.x); y0.y = fmaf(ni, a0.y, c2 * s0.y);
    y0.z = fmaf(ni, a0.z, c2 * s0.z); y0.w = fmaf(ni, a0.w, c2 * s0.w);
    y1.x = fmaf(ni, a1.x, c2 * s1.x); y1.y = fmaf(ni, a1.y, c2 * s1.y);
    y1.z = fmaf(ni, a1.z, c2 * s1.z); y1.w = fmaf(ni, a1.w, c2 * s1.w);

    size_t base = (size_t)i * D + 4 * lane;
    split_store4(g_yhi + base,       g_ylo + base,       y0);
    split_store4(g_yhi + base + 128, g_ylo + base + 128, y1);
    if (lane == 0) g_bcoef[i] = ni * (s + ni);
}

// ---------------- WMMA GEMM ------------------------------------------------
#define GBM 128
#define GBN 128
#define GBK 32
#define NSTAGE 24
#define TS 40
#define TILE_BYTES (128 * TS * 2)
#define STG_LD 132
#define SMEM_BIAS 0
#define SMEM_TILES 512
#define GEMM_SMEM (512 + 128 * STG_LD * 4)

__global__ __launch_bounds__(256, 2) void k_gemm_wmma(const float* __restrict__ bias,
                                                      float* __restrict__ out, int M) {
    extern __shared__ char sm[];
    float* s_bias = (float*)(sm + SMEM_BIAS);
    char*  tiles  = sm + SMEM_TILES;
    __nv_bfloat16* Abuf[2] = {(__nv_bfloat16*)(tiles),
                              (__nv_bfloat16*)(tiles + 2 * TILE_BYTES)};
    __nv_bfloat16* Bbuf[2] = {(__nv_bfloat16*)(tiles + TILE_BYTES),
                              (__nv_bfloat16*)(tiles + 3 * TILE_BYTES)};
    float* stg = (float*)tiles;

    int tid = threadIdx.x;
    int wid = tid >> 5;
    int wm  = wid & 3;
    int wn  = wid >> 2;
    int bm  = blockIdx.x * GBM;
    int bn  = blockIdx.y * GBN;

    if (tid < 128) s_bias[tid] = bias[bn + tid];

    wmma::fragment<wmma::accumulator, 16, 16, 16, float> acc[2][4];
#pragma unroll
    for (int i = 0; i < 2; i++)
#pragma unroll
        for (int jj = 0; jj < 4; jj++) wmma::fill_fragment(acc[i][jj], 0.f);

    auto issue = [&](int c) {
        int seg = c >> 3;
        int kk  = (c & 7) * GBK;
        const __nv_bfloat16* Asrc = (seg == 2) ? g_ylo : g_yhi;
        const __nv_bfloat16* Bsrc = (seg == 1) ? g_Wlo : g_Whi;
        __nv_bfloat16* Ad = Abuf[c & 1];
        __nv_bfloat16* Bd = Bbuf[c & 1];
#pragma unroll
        for (int r = 0; r < 2; r++) {
            int u   = tid + r * 256;
            int row = u >> 2;
            int c8  = (u & 3) * 8;
            cp16(Ad + row * TS + c8, Asrc + (size_t)(bm + row) * D + kk + c8);
            cp16(Bd + row * TS + c8, Bsrc + (size_t)(bn + row) * D + kk + c8);
        }
    };

    issue(0);
    CP_COMMIT();
    for (int c = 0; c < NSTAGE; c++) {
        if (c + 1 < NSTAGE) { issue(c + 1); CP_COMMIT(); CP_WAIT(1); }
        else                { CP_WAIT(0); }
        __syncthreads();

        const __nv_bfloat16* As = Abuf[c & 1];
        const __nv_bfloat16* Bs = Bbuf[c & 1];
#pragma unroll
        for (int ks = 0; ks < GBK; ks += 16) {
            wmma::fragment<wmma::matrix_a, 16, 16, 16, __nv_bfloat16, wmma::row_major> af[2];
            wmma::fragment<wmma::matrix_b, 16, 16, 16, __nv_bfloat16, wmma::col_major> bf[4];
#pragma unroll
            for (int i = 0; i < 2; i++)
                wmma::load_matrix_sync(af[i], As + (wm * 32 + i * 16) * TS + ks, TS);
#pragma unroll
            for (int jj = 0; jj < 4; jj++)
                wmma::load_matrix_sync(bf[jj], Bs + (wn * 64 + jj * 16) * TS + ks, TS);
#pragma unroll
            for (int i = 0; i < 2; i++)
#pragma unroll
                for (int jj = 0; jj < 4; jj++)
                    wmma::mma_sync(acc[i][jj], af[i], bf[jj], acc[i][jj]);
        }
        __syncthreads();
    }

#pragma unroll
    for (int i = 0; i < 2; i++)
#pragma unroll
        for (int jj = 0; jj < 4; jj++)
            wmma::store_matrix_sync(stg + (size_t)(wm * 32 + i * 16) * STG_LD + wn * 64 + jj * 16,
                                    acc[i][jj], STG_LD, wmma::mem_row_major);
    __syncthreads();

    int row  = tid >> 1;
    int half = tid & 1;
    int m    = bm + row;
    if (m < M) {
        float bc = g_bcoef[m];
        const float* sr = stg + (size_t)row * STG_LD + half * 64;
        float*       op = out + (size_t)m * D + bn + half * 64;
        const float* bl = s_bias + half * 64;
#pragma unroll
        for (int q = 0; q < 16; q++) {
            float4 v;
            v.x = sr[4 * q + 0] + bc * bl[4 * q + 0];
            v.y = sr[4 * q + 1] + bc * bl[4 * q + 1];
            v.z = sr[4 * q + 2] + bc * bl[4 * q + 2];
            v.w = sr[4 * q + 3] + bc * bl[4 * q + 3];
            *(float4*)(op + 4 * q) = v;
        }
    }
}

// ------------------------------------------------------------- entry point
extern "C" void kernel_launch(void* const* d_in, const int* in_sizes, int n_in,
                              void* d_out, int out_size) {
    const float* x    = (const float*)d_in[0];
    const float* W    = (const float*)d_in[1];
    const float* bias = (const float*)d_in[2];
    const int*   rows = (const int*)d_in[3];
    const int*   cols = (const int*)d_in[4];
    int N = in_sizes[0] / D;
    int E = in_sizes[3];
    if (N > NODES_MAX) N = NODES_MAX;
    if (E > EDGES_MAX) E = EDGES_MAX;

    cudaFuncSetAttribute(k_gemm_wmma, cudaFuncAttributeMaxDynamicSharedMemorySize, GEMM_SMEM);

    k_zero<<<(N + 255) / 256, 256>>>(N);
    k_hist<<<(E + 255) / 256, 256>>>(rows, E);
    k_wsplit<<<(D * D + 255) / 256, 256>>>(W);
    k_part<<<SCAN_B, 1024>>>(N);
    k_top<<<1, 32>>>();
    k_down<<<SCAN_B, 1024>>>(N);
    k_scatter<<<(E + 255) / 256, 256>>>(rows, cols, E);
    k_aggregate<<<(N * 32 + 255) / 256, 256>>>(x, N);
    dim3 grid((N + GBM - 1) / GBM, D / GBN);
    k_gemm_wmma<<<grid, 256, GEMM_SMEM>>>(bias, (float*)d_out, N);
}

// round 5
// speedup vs baseline: 1.6003x; 1.0267x over previous
#include <cuda_runtime.h>
#include <cuda_bf16.h>
#include <mma.h>
#include <math.h>
#include <cstdint>

using namespace nvcuda;

// Problem constants
#define NODES_MAX 100000
#define EDGES_MAX 3200000
#define D 256
#define NPAD 100224           // 783*128 padded M
#define SCAN_B 98

// ---------------- scratch (device globals; no runtime allocation) ----------
__device__ __nv_bfloat16 g_yhi[(size_t)NPAD * D];
__device__ __nv_bfloat16 g_ylo[(size_t)NPAD * D];
__device__ __nv_bfloat16 g_Whi[D * D];
__device__ __nv_bfloat16 g_Wlo[D * D];
__device__ int   g_colidx[EDGES_MAX];
__device__ int   g_deg[NODES_MAX];
__device__ int   g_pos[NODES_MAX];
__device__ int   g_rowptr[NODES_MAX + 1];
__device__ float g_norm[NODES_MAX];
__device__ float g_bcoef[NODES_MAX];
__device__ int   g_part[SCAN_B];
__device__ int   g_partscan[SCAN_B];

// ---------------- helpers --------------------------------------------------
__device__ __forceinline__ uint32_t smem_u32(const void* p) {
    uint32_t a;
    asm("{ .reg .u64 t; cvta.to.shared.u64 t, %1; cvt.u32.u64 %0, t; }" : "=r"(a) : "l"(p));
    return a;
}
__device__ __forceinline__ void cp16(void* dst, const void* src) {
    uint32_t d = smem_u32(dst);
    asm volatile("cp.async.cg.shared.global [%0], [%1], 16;" :: "r"(d), "l"(src) : "memory");
}
#define CP_COMMIT() asm volatile("cp.async.commit_group;" ::: "memory")
#define CP_WAIT(n)  asm volatile("cp.async.wait_group %0;" :: "n"(n) : "memory")

// ---------------------------------------------------------------- CSR build
__global__ void k_zero(int n) {
    int i = blockIdx.x * blockDim.x + threadIdx.x;
    if (i < n) g_deg[i] = 0;
}
__global__ void k_hist(const int* __restrict__ rows, int E) {
    int i = blockIdx.x * blockDim.x + threadIdx.x;
    if (i < E) atomicAdd(&g_deg[rows[i]], 1);
}

__global__ __launch_bounds__(1024) void k_part(int n) {
    __shared__ int wsum[32];
    int i = blockIdx.x * 1024 + threadIdx.x;
    int v = (i < n) ? g_deg[i] : 0;
    int s = v;
#pragma unroll
    for (int o = 16; o > 0; o >>= 1) s += __shfl_down_sync(0xffffffffu, s, o);
    if ((threadIdx.x & 31) == 0) wsum[threadIdx.x >> 5] = s;
    __syncthreads();
    if (threadIdx.x < 32) {
        int t = wsum[threadIdx.x];
#pragma unroll
        for (int o = 16; o > 0; o >>= 1) t += __shfl_down_sync(0xffffffffu, t, o);
        if (threadIdx.x == 0) g_part[blockIdx.x] = t;
    }
}

__global__ void k_top() {
    int lane = threadIdx.x;
    int run = 0;
    for (int base = 0; base < SCAN_B; base += 32) {
        int idx = base + lane;
        int v = (idx < SCAN_B) ? g_part[idx] : 0;
        int x = v;
#pragma unroll
        for (int o = 1; o < 32; o <<= 1) {
            int y = __shfl_up_sync(0xffffffffu, x, o);
            if (lane >= o) x += y;
        }
        if (idx < SCAN_B) g_partscan[idx] = run + x - v;
        run += __shfl_sync(0xffffffffu, x, 31);
    }
}

__global__ __launch_bounds__(1024) void k_down(int n) {
    __shared__ int sh[1024];
    int t = threadIdx.x;
    int i = blockIdx.x * 1024 + t;
    int d = (i < n) ? g_deg[i] : 0;
    sh[t] = d;
    __syncthreads();
#pragma unroll
    for (int o = 1; o < 1024; o <<= 1) {
        int v = (t >= o) ? sh[t - o] : 0;
        __syncthreads();
        sh[t] += v;
        __syncthreads();
    }
    int excl = sh[t] - d + g_partscan[blockIdx.x];
    if (i < n) {
        g_rowptr[i] = excl;
        g_pos[i]    = excl;
        g_norm[i]   = rsqrtf(1.0f + (float)d);
        if (i == n - 1) g_rowptr[n] = excl + d;
    }
}

__global__ void k_scatter(const int* __restrict__ rows, const int* __restrict__ cols, int E) {
    int i = blockIdx.x * blockDim.x + threadIdx.x;
    if (i < E) {
        int r = rows[i];
        int p = atomicAdd(&g_pos[r], 1);
        g_colidx[p] = cols[i];
    }
}

// ---------------- W split into bf16 hi/lo ----------------------------------
__global__ void k_wsplit(const float* __restrict__ W) {
    int i = blockIdx.x * blockDim.x + threadIdx.x;
    if (i < D * D) {
        float v = W[i];
        __nv_bfloat16 h = __float2bfloat16(v);
        g_Whi[i] = h;
        g_Wlo[i] = __float2bfloat16(v - __bfloat162float(h));
    }
}

// ---------------- per-node gather-reduce, emit bf16 hi/lo ------------------
__device__ __forceinline__ void split_store4(__nv_bfloat16* hp, __nv_bfloat16* lp, float4 v) {
    __nv_bfloat16 h0 = __float2bfloat16(v.x), h1 = __float2bfloat16(v.y);
    __nv_bfloat16 h2 = __float2bfloat16(v.z), h3 = __float2bfloat16(v.w);
    __nv_bfloat16 l0 = __float2bfloat16(v.x - __bfloat162float(h0));
    __nv_bfloat16 l1 = __float2bfloat16(v.y - __bfloat162float(h1));
    __nv_bfloat16 l2 = __float2bfloat16(v.z - __bfloat162float(h2));
    __nv_bfloat16 l3 = __float2bfloat16(v.w - __bfloat162float(h3));
    uint2 hu, lu;
    hu.x = ((uint32_t)__bfloat16_as_ushort(h1) << 16) | __bfloat16_as_ushort(h0);
    hu.y = ((uint32_t)__bfloat16_as_ushort(h3) << 16) | __bfloat16_as_ushort(h2);
    lu.x = ((uint32_t)__bfloat16_as_ushort(l1) << 16) | __bfloat16_as_ushort(l0);
    lu.y = ((uint32_t)__bfloat16_as_ushort(l3) << 16) | __bfloat16_as_ushort(l2);
    *(uint2*)hp = hu;
    *(uint2*)lp = lu;
}

__global__ void k_aggregate(const float* __restrict__ x, int n) {
    int gw   = (blockIdx.x * blockDim.x + threadIdx.x) >> 5;
    int lane = threadIdx.x & 31;
    if (gw >= n) return;
    int i   = gw;
    int beg = g_rowptr[i];
    int end = g_rowptr[i + 1];

    float4 a0 = make_float4(0.f, 0.f, 0.f, 0.f);
    float4 a1 = make_float4(0.f, 0.f, 0.f, 0.f);
    float  s  = 0.f;

    int j = beg;
    for (; j + 1 < end; j += 2) {
        int   c0 = __ldg(&g_colidx[j]);
        int   c1 = __ldg(&g_colidx[j + 1]);
        float n0 = __ldg(&g_norm[c0]);
        float n1 = __ldg(&g_norm[c1]);
        const float4* xr0 = (const float4*)(x + (size_t)c0 * D);
        const float4* xr1 = (const float4*)(x + (size_t)c1 * D);
        float4 u0 = __ldg(&xr0[lane]);
        float4 u1 = __ldg(&xr0[lane + 32]);
        float4 v0 = __ldg(&xr1[lane]);
        float4 v1 = __ldg(&xr1[lane + 32]);
        s += n0 + n1;
        a0.x = fmaf(n0, u0.x, a0.x); a0.y = fmaf(n0, u0.y, a0.y);
        a0.z = fmaf(n0, u0.z, a0.z); a0.w = fmaf(n0, u0.w, a0.w);
        a1.x = fmaf(n0, u1.x, a1.x); a1.y = fmaf(n0, u1.y, a1.y);
        a1.z = fmaf(n0, u1.z, a1.z); a1.w = fmaf(n0, u1.w, a1.w);
        a0.x = fmaf(n1, v0.x, a0.x); a0.y = fmaf(n1, v0.y, a0.y);
        a0.z = fmaf(n1, v0.z, a0.z); a0.w = fmaf(n1, v0.w, a0.w);
        a1.x = fmaf(n1, v1.x, a1.x); a1.y = fmaf(n1, v1.y, a1.y);
        a1.z = fmaf(n1, v1.z, a1.z); a1.w = fmaf(n1, v1.w, a1.w);
    }
    if (j < end) {
        int   c  = __ldg(&g_colidx[j]);
        float nc = __ldg(&g_norm[c]);
        s += nc;
        const float4* xr = (const float4*)(x + (size_t)c * D);
        float4 v0 = __ldg(&xr[lane]);
        float4 v1 = __ldg(&xr[lane + 32]);
        a0.x = fmaf(nc, v0.x, a0.x); a0.y = fmaf(nc, v0.y, a0.y);
        a0.z = fmaf(nc, v0.z, a0.z); a0.w = fmaf(nc, v0.w, a0.w);
        a1.x = fmaf(nc, v1.x, a1.x); a1.y = fmaf(nc, v1.y, a1.y);
        a1.z = fmaf(nc, v1.z, a1.z); a1.w = fmaf(nc, v1.w, a1.w);
    }

    float ni = g_norm[i];
    float c2 = ni * ni;
    const float4* xi = (const float4*)(x + (size_t)i * D);
    float4 s0 = __ldg(&xi[lane]);
    float4 s1 = __ldg(&xi[lane + 32]);

    float4 y0, y1;
    y0.x = fmaf(ni, a0.x, c2 * s0.x); y0.y = fmaf(ni, a0.y, c2 * s0.y);
    y0.z = fmaf(ni, a0.z, c2 * s0.z); y0.w = fmaf(ni, a0.w, c2 * s0.w);
    y1.x = fmaf(ni, a1.x, c2 * s1.x); y1.y = fmaf(ni, a1.y, c2 * s1.y);
    y1.z = fmaf(ni, a1.z, c2 * s1.z); y1.w = fmaf(ni, a1.w, c2 * s1.w);

    size_t base = (size_t)i * D + 4 * lane;
    split_store4(g_yhi + base,       g_ylo + base,       y0);
    split_store4(g_yhi + base + 128, g_ylo + base + 128, y1);
    if (lane == 0) g_bcoef[i] = ni * (s + ni);
}

// ---------------- WMMA GEMM v2 ---------------------------------------------
// Stages 0..7:  A = yhi[k],  B0 = Whi[k], B1 = Wlo[k]  (two MMA passes, same acc)
// Stages 8..15: A = ylo[k],  B0 = Whi[k]               (one MMA pass)
// A loaded once per k-chunk. grid = (2, mtiles) so both N-halves of the same
// A tile run adjacently for L2 reuse.
#define GBM 128
#define GBN 128
#define GBK 32
#define NST 16
#define TS 40
#define TILE_BYTES (128 * TS * 2)           // 10240
#define STG_LD 132
#define SMEM_BIAS 0
#define SMEM_TILES 512
// layout: [A0 B0a B1a | A1 B0b B1b] = 6 tiles = 61440; staging 67584 dominates
#define GEMM_SMEM (512 + 128 * STG_LD * 4)

__global__ __launch_bounds__(256, 2) void k_gemm_wmma(const float* __restrict__ bias,
                                                      float* __restrict__ out, int M) {
    extern __shared__ char sm[];
    float* s_bias = (float*)(sm + SMEM_BIAS);
    char*  tiles  = sm + SMEM_TILES;
    __nv_bfloat16* Abuf[2]  = {(__nv_bfloat16*)(tiles),
                               (__nv_bfloat16*)(tiles + 3 * TILE_BYTES)};
    __nv_bfloat16* B0buf[2] = {(__nv_bfloat16*)(tiles + 1 * TILE_BYTES),
                               (__nv_bfloat16*)(tiles + 4 * TILE_BYTES)};
    __nv_bfloat16* B1buf[2] = {(__nv_bfloat16*)(tiles + 2 * TILE_BYTES),
                               (__nv_bfloat16*)(tiles + 5 * TILE_BYTES)};
    float* stg = (float*)tiles;

    int tid = threadIdx.x;
    int wid = tid >> 5;
    int wm  = wid & 3;
    int wn  = wid >> 2;
    int bn  = blockIdx.x * GBN;
    int bm  = blockIdx.y * GBM;

    if (tid < 128) s_bias[tid] = bias[bn + tid];

    wmma::fragment<wmma::accumulator, 16, 16, 16, float> acc[2][4];
#pragma unroll
    for (int i = 0; i < 2; i++)
#pragma unroll
        for (int jj = 0; jj < 4; jj++) wmma::fill_fragment(acc[i][jj], 0.f);

    auto issue = [&](int c) {
        int seg = c >> 3;                 // 0: yhi stage, 1: ylo stage
        int kk  = (c & 7) * GBK;
        const __nv_bfloat16* Asrc = seg ? g_ylo : g_yhi;
        __nv_bfloat16* Ad  = Abuf[c & 1];
        __nv_bfloat16* B0d = B0buf[c & 1];
        __nv_bfloat16* B1d = B1buf[c & 1];
#pragma unroll
        for (int r = 0; r < 2; r++) {
            int u   = tid + r * 256;      // 512 16B-chunks per tile
            int row = u >> 2;
            int c8  = (u & 3) * 8;
            cp16(Ad  + row * TS + c8, Asrc  + (size_t)(bm + row) * D + kk + c8);
            cp16(B0d + row * TS + c8, g_Whi + (size_t)(bn + row) * D + kk + c8);
        }
        if (seg == 0) {
#pragma unroll
            for (int r = 0; r < 2; r++) {
                int u   = tid + r * 256;
                int row = u >> 2;
                int c8  = (u & 3) * 8;
                cp16(B1d + row * TS + c8, g_Wlo + (size_t)(bn + row) * D + kk + c8);
            }
        }
    };

    issue(0);
    CP_COMMIT();
    for (int c = 0; c < NST; c++) {
        if (c + 1 < NST) { issue(c + 1); CP_COMMIT(); CP_WAIT(1); }
        else             { CP_WAIT(0); }
        __syncthreads();

        const __nv_bfloat16* As = Abuf[c & 1];
        int npass = (c < 8) ? 2 : 1;
        for (int p = 0; p < npass; p++) {
            const __nv_bfloat16* Bs = (p == 0) ? B0buf[c & 1] : B1buf[c & 1];
#pragma unroll
            for (int ks = 0; ks < GBK; ks += 16) {
                wmma::fragment<wmma::matrix_a, 16, 16, 16, __nv_bfloat16, wmma::row_major> af[2];
                wmma::fragment<wmma::matrix_b, 16, 16, 16, __nv_bfloat16, wmma::col_major> bf[4];
#pragma unroll
                for (int i = 0; i < 2; i++)
                    wmma::load_matrix_sync(af[i], As + (wm * 32 + i * 16) * TS + ks, TS);
#pragma unroll
                for (int jj = 0; jj < 4; jj++)
                    wmma::load_matrix_sync(bf[jj], Bs + (wn * 64 + jj * 16) * TS + ks, TS);
#pragma unroll
                for (int i = 0; i < 2; i++)
#pragma unroll
                    for (int jj = 0; jj < 4; jj++)
                        wmma::mma_sync(acc[i][jj], af[i], bf[jj], acc[i][jj]);
            }
        }
        __syncthreads();
    }

#pragma unroll
    for (int i = 0; i < 2; i++)
#pragma unroll
        for (int jj = 0; jj < 4; jj++)
            wmma::store_matrix_sync(stg + (size_t)(wm * 32 + i * 16) * STG_LD + wn * 64 + jj * 16,
                                    acc[i][jj], STG_LD, wmma::mem_row_major);
    __syncthreads();

    int row  = tid >> 1;
    int half = tid & 1;
    int m    = bm + row;
    if (m < M) {
        float bc = g_bcoef[m];
        const float* sr = stg + (size_t)row * STG_LD + half * 64;
        float*       op = out + (size_t)m * D + bn + half * 64;
        const float* bl = s_bias + half * 64;
#pragma unroll
        for (int q = 0; q < 16; q++) {
            float4 v;
            v.x = sr[4 * q + 0] + bc * bl[4 * q + 0];
            v.y = sr[4 * q + 1] + bc * bl[4 * q + 1];
            v.z = sr[4 * q + 2] + bc * bl[4 * q + 2];
            v.w = sr[4 * q + 3] + bc * bl[4 * q + 3];
            *(float4*)(op + 4 * q) = v;
        }
    }
}

// ------------------------------------------------------------- entry point
extern "C" void kernel_launch(void* const* d_in, const int* in_sizes, int n_in,
                              void* d_out, int out_size) {
    const float* x    = (const float*)d_in[0];
    const float* W    = (const float*)d_in[1];
    const float* bias = (const float*)d_in[2];
    const int*   rows = (const int*)d_in[3];
    const int*   cols = (const int*)d_in[4];
    int N = in_sizes[0] / D;
    int E = in_sizes[3];
    if (N > NODES_MAX) N = NODES_MAX;
    if (E > EDGES_MAX) E = EDGES_MAX;

    cudaFuncSetAttribute(k_gemm_wmma, cudaFuncAttributeMaxDynamicSharedMemorySize, GEMM_SMEM);

    k_zero<<<(N + 255) / 256, 256>>>(N);
    k_hist<<<(E + 255) / 256, 256>>>(rows, E);
    k_wsplit<<<(D * D + 255) / 256, 256>>>(W);
    k_part<<<SCAN_B, 1024>>>(N);
    k_top<<<1, 32>>>();
    k_down<<<SCAN_B, 1024>>>(N);
    k_scatter<<<(E + 255) / 256, 256>>>(rows, cols, E);
    k_aggregate<<<(N * 32 + 255) / 256, 256>>>(x, N);
    dim3 grid(D / GBN, (N + GBM - 1) / GBM);
    k_gemm_wmma<<<grid, 256, GEMM_SMEM>>>(bias, (float*)d_out, N);
}

// round 6
// speedup vs baseline: 1.9230x; 1.2016x over previous
#include <cuda_runtime.h>
#include <cuda_bf16.h>
#include <cuda_fp16.h>
#include <mma.h>
#include <math.h>
#include <cstdint>

using namespace nvcuda;

// Problem constants
#define NODES_MAX 100000
#define EDGES_MAX 3200000
#define D 256
#define NPAD 100224           // 783*128 padded M
#define SCAN_B 98

// ---------------- scratch (device globals; no runtime allocation) ----------
__device__ __nv_bfloat16 g_yhi[(size_t)NPAD * D];
__device__ __nv_bfloat16 g_ylo[(size_t)NPAD * D];
__device__ __half        g_xh[(size_t)NODES_MAX * D];   // fp16 copy of x (51.2 MB)
__device__ __nv_bfloat16 g_Whi[D * D];
__device__ __nv_bfloat16 g_Wlo[D * D];
__device__ int   g_colidx[EDGES_MAX];
__device__ int   g_deg[NODES_MAX];
__device__ int   g_pos[NODES_MAX];
__device__ int   g_rowptr[NODES_MAX + 1];
__device__ float g_norm[NODES_MAX];
__device__ float g_bcoef[NODES_MAX];
__device__ int   g_part[SCAN_B];
__device__ int   g_partscan[SCAN_B];

// ---------------- helpers --------------------------------------------------
__device__ __forceinline__ uint32_t smem_u32(const void* p) {
    uint32_t a;
    asm("{ .reg .u64 t; cvta.to.shared.u64 t, %1; cvt.u32.u64 %0, t; }" : "=r"(a) : "l"(p));
    return a;
}
__device__ __forceinline__ void cp16(void* dst, const void* src) {
    uint32_t d = smem_u32(dst);
    asm volatile("cp.async.cg.shared.global [%0], [%1], 16;" :: "r"(d), "l"(src) : "memory");
}
#define CP_COMMIT() asm volatile("cp.async.commit_group;" ::: "memory")
#define CP_WAIT(n)  asm volatile("cp.async.wait_group %0;" :: "n"(n) : "memory")

// ---------------------------------------------------------------- CSR build
__global__ void k_zero(int n) {
    int i = blockIdx.x * blockDim.x + threadIdx.x;
    if (i < n) g_deg[i] = 0;
}
__global__ void k_hist(const int* __restrict__ rows, int E) {
    int i = blockIdx.x * blockDim.x + threadIdx.x;
    if (i < E) atomicAdd(&g_deg[rows[i]], 1);
}

__global__ __launch_bounds__(1024) void k_part(int n) {
    __shared__ int wsum[32];
    int i = blockIdx.x * 1024 + threadIdx.x;
    int v = (i < n) ? g_deg[i] : 0;
    int s = v;
#pragma unroll
    for (int o = 16; o > 0; o >>= 1) s += __shfl_down_sync(0xffffffffu, s, o);
    if ((threadIdx.x & 31) == 0) wsum[threadIdx.x >> 5] = s;
    __syncthreads();
    if (threadIdx.x < 32) {
        int t = wsum[threadIdx.x];
#pragma unroll
        for (int o = 16; o > 0; o >>= 1) t += __shfl_down_sync(0xffffffffu, t, o);
        if (threadIdx.x == 0) g_part[blockIdx.x] = t;
    }
}

__global__ void k_top() {
    int lane = threadIdx.x;
    int run = 0;
    for (int base = 0; base < SCAN_B; base += 32) {
        int idx = base + lane;
        int v = (idx < SCAN_B) ? g_part[idx] : 0;
        int x = v;
#pragma unroll
        for (int o = 1; o < 32; o <<= 1) {
            int y = __shfl_up_sync(0xffffffffu, x, o);
            if (lane >= o) x += y;
        }
        if (idx < SCAN_B) g_partscan[idx] = run + x - v;
        run += __shfl_sync(0xffffffffu, x, 31);
    }
}

__global__ __launch_bounds__(1024) void k_down(int n) {
    __shared__ int sh[1024];
    int t = threadIdx.x;
    int i = blockIdx.x * 1024 + t;
    int d = (i < n) ? g_deg[i] : 0;
    sh[t] = d;
    __syncthreads();
#pragma unroll
    for (int o = 1; o < 1024; o <<= 1) {
        int v = (t >= o) ? sh[t - o] : 0;
        __syncthreads();
        sh[t] += v;
        __syncthreads();
    }
    int excl = sh[t] - d + g_partscan[blockIdx.x];
    if (i < n) {
        g_rowptr[i] = excl;
        g_pos[i]    = excl;
        g_norm[i]   = rsqrtf(1.0f + (float)d);
        if (i == n - 1) g_rowptr[n] = excl + d;
    }
}

__global__ void k_scatter(const int* __restrict__ rows, const int* __restrict__ cols, int E) {
    int i = blockIdx.x * blockDim.x + threadIdx.x;
    if (i < E) {
        int r = rows[i];
        int p = atomicAdd(&g_pos[r], 1);
        g_colidx[p] = cols[i];
    }
}

// ---------------- conversions ---------------------------------------------
__global__ void k_wsplit(const float* __restrict__ W) {
    int i = blockIdx.x * blockDim.x + threadIdx.x;
    if (i < D * D) {
        float v = W[i];
        __nv_bfloat16 h = __float2bfloat16(v);
        g_Whi[i] = h;
        g_Wlo[i] = __float2bfloat16(v - __bfloat162float(h));
    }
}

// x fp32 -> fp16 (4 elems per thread)
__global__ void k_xhalf(const float* __restrict__ x, int total4) {
    int i = blockIdx.x * blockDim.x + threadIdx.x;
    if (i < total4) {
        float4 v = __ldg(&((const float4*)x)[i]);
        __half2 a = __floats2half2_rn(v.x, v.y);
        __half2 b = __floats2half2_rn(v.z, v.w);
        uint2 u;
        u.x = *(uint32_t*)&a;
        u.y = *(uint32_t*)&b;
        *(uint2*)(g_xh + (size_t)i * 4) = u;
    }
}

// ---------------- per-node gather-reduce (fp16 gather, fp32 self) ----------
__device__ __forceinline__ void split_store4(__nv_bfloat16* hp, __nv_bfloat16* lp, float4 v) {
    __nv_bfloat16 h0 = __float2bfloat16(v.x), h1 = __float2bfloat16(v.y);
    __nv_bfloat16 h2 = __float2bfloat16(v.z), h3 = __float2bfloat16(v.w);
    __nv_bfloat16 l0 = __float2bfloat16(v.x - __bfloat162float(h0));
    __nv_bfloat16 l1 = __float2bfloat16(v.y - __bfloat162float(h1));
    __nv_bfloat16 l2 = __float2bfloat16(v.z - __bfloat162float(h2));
    __nv_bfloat16 l3 = __float2bfloat16(v.w - __bfloat162float(h3));
    uint2 hu, lu;
    hu.x = ((uint32_t)__bfloat16_as_ushort(h1) << 16) | __bfloat16_as_ushort(h0);
    hu.y = ((uint32_t)__bfloat16_as_ushort(h3) << 16) | __bfloat16_as_ushort(h2);
    lu.x = ((uint32_t)__bfloat16_as_ushort(l1) << 16) | __bfloat16_as_ushort(l0);
    lu.y = ((uint32_t)__bfloat16_as_ushort(l3) << 16) | __bfloat16_as_ushort(l2);
    *(uint2*)hp = hu;
    *(uint2*)lp = lu;
}

__device__ __forceinline__ void acc_half8(float* a, uint4 v, float nc) {
    __half2 h0 = *(__half2*)&v.x, h1 = *(__half2*)&v.y;
    __half2 h2 = *(__half2*)&v.z, h3 = *(__half2*)&v.w;
    float2 f0 = __half22float2(h0), f1 = __half22float2(h1);
    float2 f2 = __half22float2(h2), f3 = __half22float2(h3);
    a[0] = fmaf(nc, f0.x, a[0]); a[1] = fmaf(nc, f0.y, a[1]);
    a[2] = fmaf(nc, f1.x, a[2]); a[3] = fmaf(nc, f1.y, a[3]);
    a[4] = fmaf(nc, f2.x, a[4]); a[5] = fmaf(nc, f2.y, a[5]);
    a[6] = fmaf(nc, f3.x, a[6]); a[7] = fmaf(nc, f3.y, a[7]);
}

__global__ void k_aggregate(const float* __restrict__ x, int n) {
    int gw   = (blockIdx.x * blockDim.x + threadIdx.x) >> 5;
    int lane = threadIdx.x & 31;
    if (gw >= n) return;
    int i   = gw;
    int beg = g_rowptr[i];
    int end = g_rowptr[i + 1];

    float a[8] = {0.f, 0.f, 0.f, 0.f, 0.f, 0.f, 0.f, 0.f};
    float s = 0.f;

    int j = beg;
    for (; j + 1 < end; j += 2) {
        int   c0 = __ldg(&g_colidx[j]);
        int   c1 = __ldg(&g_colidx[j + 1]);
        float n0 = __ldg(&g_norm[c0]);
        float n1 = __ldg(&g_norm[c1]);
        uint4 v0 = __ldg((const uint4*)(g_xh + (size_t)c0 * D) + lane);
        uint4 v1 = __ldg((const uint4*)(g_xh + (size_t)c1 * D) + lane);
        s += n0 + n1;
        acc_half8(a, v0, n0);
        acc_half8(a, v1, n1);
    }
    if (j < end) {
        int   c  = __ldg(&g_colidx[j]);
        float nc = __ldg(&g_norm[c]);
        s += nc;
        uint4 v = __ldg((const uint4*)(g_xh + (size_t)c * D) + lane);
        acc_half8(a, v, nc);
    }

    float ni = g_norm[i];
    float c2 = ni * ni;
    // self term fp32-exact: lane covers 8 contiguous elements
    const float4* xi = (const float4*)(x + (size_t)i * D + 8 * lane);
    float4 s0 = __ldg(&xi[0]);
    float4 s1 = __ldg(&xi[1]);

    float4 y0, y1;
    y0.x = fmaf(ni, a[0], c2 * s0.x); y0.y = fmaf(ni, a[1], c2 * s0.y);
    y0.z = fmaf(ni, a[2], c2 * s0.z); y0.w = fmaf(ni, a[3], c2 * s0.w);
    y1.x = fmaf(ni, a[4], c2 * s1.x); y1.y = fmaf(ni, a[5], c2 * s1.y);
    y1.z = fmaf(ni, a[6], c2 * s1.z); y1.w = fmaf(ni, a[7], c2 * s1.w);

    size_t base = (size_t)i * D + 8 * lane;
    split_store4(g_yhi + base,     g_ylo + base,     y0);
    split_store4(g_yhi + base + 4, g_ylo + base + 4, y1);
    if (lane == 0) g_bcoef[i] = ni * (s + ni);
}

// ---------------- WMMA GEMM (unchanged from R5) ----------------------------
#define GBM 128
#define GBN 128
#define GBK 32
#define NST 16
#define TS 40
#define TILE_BYTES (128 * TS * 2)
#define STG_LD 132
#define SMEM_BIAS 0
#define SMEM_TILES 512
#define GEMM_SMEM (512 + 128 * STG_LD * 4)

__global__ __launch_bounds__(256, 2) void k_gemm_wmma(const float* __restrict__ bias,
                                                      float* __restrict__ out, int M) {
    extern __shared__ char sm[];
    float* s_bias = (float*)(sm + SMEM_BIAS);
    char*  tiles  = sm + SMEM_TILES;
    __nv_bfloat16* Abuf[2]  = {(__nv_bfloat16*)(tiles),
                               (__nv_bfloat16*)(tiles + 3 * TILE_BYTES)};
    __nv_bfloat16* B0buf[2] = {(__nv_bfloat16*)(tiles + 1 * TILE_BYTES),
                               (__nv_bfloat16*)(tiles + 4 * TILE_BYTES)};
    __nv_bfloat16* B1buf[2] = {(__nv_bfloat16*)(tiles + 2 * TILE_BYTES),
                               (__nv_bfloat16*)(tiles + 5 * TILE_BYTES)};
    float* stg = (float*)tiles;

    int tid = threadIdx.x;
    int wid = tid >> 5;
    int wm  = wid & 3;
    int wn  = wid >> 2;
    int bn  = blockIdx.x * GBN;
    int bm  = blockIdx.y * GBM;

    if (tid < 128) s_bias[tid] = bias[bn + tid];

    wmma::fragment<wmma::accumulator, 16, 16, 16, float> acc[2][4];
#pragma unroll
    for (int i = 0; i < 2; i++)
#pragma unroll
        for (int jj = 0; jj < 4; jj++) wmma::fill_fragment(acc[i][jj], 0.f);

    auto issue = [&](int c) {
        int seg = c >> 3;
        int kk  = (c & 7) * GBK;
        const __nv_bfloat16* Asrc = seg ? g_ylo : g_yhi;
        __nv_bfloat16* Ad  = Abuf[c & 1];
        __nv_bfloat16* B0d = B0buf[c & 1];
        __nv_bfloat16* B1d = B1buf[c & 1];
#pragma unroll
        for (int r = 0; r < 2; r++) {
            int u   = tid + r * 256;
            int row = u >> 2;
            int c8  = (u & 3) * 8;
            cp16(Ad  + row * TS + c8, Asrc  + (size_t)(bm + row) * D + kk + c8);
            cp16(B0d + row * TS + c8, g_Whi + (size_t)(bn + row) * D + kk + c8);
        }
        if (seg == 0) {
#pragma unroll
            for (int r = 0; r < 2; r++) {
                int u   = tid + r * 256;
                int row = u >> 2;
                int c8  = (u & 3) * 8;
                cp16(B1d + row * TS + c8, g_Wlo + (size_t)(bn + row) * D + kk + c8);
            }
        }
    };

    issue(0);
    CP_COMMIT();
    for (int c = 0; c < NST; c++) {
        if (c + 1 < NST) { issue(c + 1); CP_COMMIT(); CP_WAIT(1); }
        else             { CP_WAIT(0); }
        __syncthreads();

        const __nv_bfloat16* As = Abuf[c & 1];
        int npass = (c < 8) ? 2 : 1;
        for (int p = 0; p < npass; p++) {
            const __nv_bfloat16* Bs = (p == 0) ? B0buf[c & 1] : B1buf[c & 1];
#pragma unroll
            for (int ks = 0; ks < GBK; ks += 16) {
                wmma::fragment<wmma::matrix_a, 16, 16, 16, __nv_bfloat16, wmma::row_major> af[2];
                wmma::fragment<wmma::matrix_b, 16, 16, 16, __nv_bfloat16, wmma::col_major> bf[4];
#pragma unroll
                for (int i = 0; i < 2; i++)
                    wmma::load_matrix_sync(af[i], As + (wm * 32 + i * 16) * TS + ks, TS);
#pragma unroll
                for (int jj = 0; jj < 4; jj++)
                    wmma::load_matrix_sync(bf[jj], Bs + (wn * 64 + jj * 16) * TS + ks, TS);
#pragma unroll
                for (int i = 0; i < 2; i++)
#pragma unroll
                    for (int jj = 0; jj < 4; jj++)
                        wmma::mma_sync(acc[i][jj], af[i], bf[jj], acc[i][jj]);
            }
        }
        __syncthreads();
    }

#pragma unroll
    for (int i = 0; i < 2; i++)
#pragma unroll
        for (int jj = 0; jj < 4; jj++)
            wmma::store_matrix_sync(stg + (size_t)(wm * 32 + i * 16) * STG_LD + wn * 64 + jj * 16,
                                    acc[i][jj], STG_LD, wmma::mem_row_major);
    __syncthreads();

    int row  = tid >> 1;
    int half = tid & 1;
    int m    = bm + row;
    if (m < M) {
        float bc = g_bcoef[m];
        const float* sr = stg + (size_t)row * STG_LD + half * 64;
        float*       op = out + (size_t)m * D + bn + half * 64;
        const float* bl = s_bias + half * 64;
#pragma unroll
        for (int q = 0; q < 16; q++) {
            float4 v;
            v.x = sr[4 * q + 0] + bc * bl[4 * q + 0];
            v.y = sr[4 * q + 1] + bc * bl[4 * q + 1];
            v.z = sr[4 * q + 2] + bc * bl[4 * q + 2];
            v.w = sr[4 * q + 3] + bc * bl[4 * q + 3];
            *(float4*)(op + 4 * q) = v;
        }
    }
}

// ------------------------------------------------------------- entry point
extern "C" void kernel_launch(void* const* d_in, const int* in_sizes, int n_in,
                              void* d_out, int out_size) {
    const float* x    = (const float*)d_in[0];
    const float* W    = (const float*)d_in[1];
    const float* bias = (const float*)d_in[2];
    const int*   rows = (const int*)d_in[3];
    const int*   cols = (const int*)d_in[4];
    int N = in_sizes[0] / D;
    int E = in_sizes[3];
    if (N > NODES_MAX) N = NODES_MAX;
    if (E > EDGES_MAX) E = EDGES_MAX;

    cudaFuncSetAttribute(k_gemm_wmma, cudaFuncAttributeMaxDynamicSharedMemorySize, GEMM_SMEM);

    k_zero<<<(N + 255) / 256, 256>>>(N);
    k_hist<<<(E + 255) / 256, 256>>>(rows, E);
    k_xhalf<<<(N * D / 4 + 255) / 256, 256>>>(x, N * D / 4);
    k_wsplit<<<(D * D + 255) / 256, 256>>>(W);
    k_part<<<SCAN_B, 1024>>>(N);
    k_top<<<1, 32>>>();
    k_down<<<SCAN_B, 1024>>>(N);
    k_scatter<<<(E + 255) / 256, 256>>>(rows, cols, E);
    k_aggregate<<<(N * 32 + 255) / 256, 256>>>(x, N);
    dim3 grid(D / GBN, (N + GBM - 1) / GBM);
    k_gemm_wmma<<<grid, 256, GEMM_SMEM>>>(bias, (float*)d_out, N);
}

// round 7
// speedup vs baseline: 2.6212x; 1.3631x over previous
#include <cuda_runtime.h>
#include <cuda_bf16.h>
#include <cuda_fp16.h>
#include <mma.h>
#include <math.h>
#include <cstdint>

using namespace nvcuda;

// Problem constants
#define NODES_MAX 100000
#define EDGES_MAX 3200000
#define D 256
#define NPAD 100224           // 783*128 padded M
#define SCAN_B 98

// ---------------- scratch (device globals; no runtime allocation) ----------
__device__ __half g_yh[(size_t)NPAD * D];              // fp16 aggregated features
__device__ __half g_xh[(size_t)NODES_MAX * D];         // fp16 copy of x (51.2 MB)
__device__ __half g_Wh[D * D];                         // fp16 W
__device__ int   g_colidx[EDGES_MAX];
__device__ int   g_deg[NODES_MAX];
__device__ int   g_pos[NODES_MAX];
__device__ int   g_rowptr[NODES_MAX + 1];
__device__ float g_norm[NODES_MAX];
__device__ float g_bcoef[NODES_MAX];
__device__ int   g_part[SCAN_B];
__device__ int   g_partscan[SCAN_B];

// ---------------- helpers --------------------------------------------------
__device__ __forceinline__ uint32_t smem_u32(const void* p) {
    uint32_t a;
    asm("{ .reg .u64 t; cvta.to.shared.u64 t, %1; cvt.u32.u64 %0, t; }" : "=r"(a) : "l"(p));
    return a;
}
__device__ __forceinline__ void cp16(void* dst, const void* src) {
    uint32_t d = smem_u32(dst);
    asm volatile("cp.async.cg.shared.global [%0], [%1], 16;" :: "r"(d), "l"(src) : "memory");
}
#define CP_COMMIT() asm volatile("cp.async.commit_group;" ::: "memory")
#define CP_WAIT(n)  asm volatile("cp.async.wait_group %0;" :: "n"(n) : "memory")

// ---------------------------------------------------------------- CSR build
__global__ void k_zero(int n) {
    int i = blockIdx.x * blockDim.x + threadIdx.x;
    if (i < n) g_deg[i] = 0;
}
__global__ void k_hist(const int* __restrict__ rows, int E) {
    int i = blockIdx.x * blockDim.x + threadIdx.x;
    if (i < E) atomicAdd(&g_deg[rows[i]], 1);
}

__global__ __launch_bounds__(1024) void k_part(int n) {
    __shared__ int wsum[32];
    int i = blockIdx.x * 1024 + threadIdx.x;
    int v = (i < n) ? g_deg[i] : 0;
    int s = v;
#pragma unroll
    for (int o = 16; o > 0; o >>= 1) s += __shfl_down_sync(0xffffffffu, s, o);
    if ((threadIdx.x & 31) == 0) wsum[threadIdx.x >> 5] = s;
    __syncthreads();
    if (threadIdx.x < 32) {
        int t = wsum[threadIdx.x];
#pragma unroll
        for (int o = 16; o > 0; o >>= 1) t += __shfl_down_sync(0xffffffffu, t, o);
        if (threadIdx.x == 0) g_part[blockIdx.x] = t;
    }
}

__global__ void k_top() {
    int lane = threadIdx.x;
    int run = 0;
    for (int base = 0; base < SCAN_B; base += 32) {
        int idx = base + lane;
        int v = (idx < SCAN_B) ? g_part[idx] : 0;
        int x = v;
#pragma unroll
        for (int o = 1; o < 32; o <<= 1) {
            int y = __shfl_up_sync(0xffffffffu, x, o);
            if (lane >= o) x += y;
        }
        if (idx < SCAN_B) g_partscan[idx] = run + x - v;
        run += __shfl_sync(0xffffffffu, x, 31);
    }
}

__global__ __launch_bounds__(1024) void k_down(int n) {
    __shared__ int sh[1024];
    int t = threadIdx.x;
    int i = blockIdx.x * 1024 + t;
    int d = (i < n) ? g_deg[i] : 0;
    sh[t] = d;
    __syncthreads();
#pragma unroll
    for (int o = 1; o < 1024; o <<= 1) {
        int v = (t >= o) ? sh[t - o] : 0;
        __syncthreads();
        sh[t] += v;
        __syncthreads();
    }
    int excl = sh[t] - d + g_partscan[blockIdx.x];
    if (i < n) {
        g_rowptr[i] = excl;
        g_pos[i]    = excl;
        g_norm[i]   = rsqrtf(1.0f + (float)d);
        if (i == n - 1) g_rowptr[n] = excl + d;
    }
}

__global__ void k_scatter(const int* __restrict__ rows, const int* __restrict__ cols, int E) {
    int i = blockIdx.x * blockDim.x + threadIdx.x;
    if (i < E) {
        int r = rows[i];
        int p = atomicAdd(&g_pos[r], 1);
        g_colidx[p] = cols[i];
    }
}

// ---------------- conversions ---------------------------------------------
__global__ void k_whalf(const float* __restrict__ W) {
    int i = blockIdx.x * blockDim.x + threadIdx.x;
    if (i < D * D) g_Wh[i] = __float2half_rn(W[i]);
}

__global__ void k_xhalf(const float* __restrict__ x, int total4) {
    int i = blockIdx.x * blockDim.x + threadIdx.x;
    if (i < total4) {
        float4 v = __ldg(&((const float4*)x)[i]);
        __half2 a = __floats2half2_rn(v.x, v.y);
        __half2 b = __floats2half2_rn(v.z, v.w);
        uint2 u;
        u.x = *(uint32_t*)&a;
        u.y = *(uint32_t*)&b;
        *(uint2*)(g_xh + (size_t)i * 4) = u;
    }
}

// ---------------- per-node gather-reduce (fp16 gather, fp32 self) ----------
__device__ __forceinline__ void acc_half8(float* a, uint4 v, float nc) {
    __half2 h0 = *(__half2*)&v.x, h1 = *(__half2*)&v.y;
    __half2 h2 = *(__half2*)&v.z, h3 = *(__half2*)&v.w;
    float2 f0 = __half22float2(h0), f1 = __half22float2(h1);
    float2 f2 = __half22float2(h2), f3 = __half22float2(h3);
    a[0] = fmaf(nc, f0.x, a[0]); a[1] = fmaf(nc, f0.y, a[1]);
    a[2] = fmaf(nc, f1.x, a[2]); a[3] = fmaf(nc, f1.y, a[3]);
    a[4] = fmaf(nc, f2.x, a[4]); a[5] = fmaf(nc, f2.y, a[5]);
    a[6] = fmaf(nc, f3.x, a[6]); a[7] = fmaf(nc, f3.y, a[7]);
}

__global__ void k_aggregate(const float* __restrict__ x, int n) {
    int gw   = (blockIdx.x * blockDim.x + threadIdx.x) >> 5;
    int lane = threadIdx.x & 31;
    if (gw >= n) return;
    int i   = gw;
    int beg = g_rowptr[i];
    int end = g_rowptr[i + 1];

    float a[8] = {0.f, 0.f, 0.f, 0.f, 0.f, 0.f, 0.f, 0.f};
    float s = 0.f;

    int j = beg;
    for (; j + 1 < end; j += 2) {
        int   c0 = __ldg(&g_colidx[j]);
        int   c1 = __ldg(&g_colidx[j + 1]);
        float n0 = __ldg(&g_norm[c0]);
        float n1 = __ldg(&g_norm[c1]);
        uint4 v0 = __ldg((const uint4*)(g_xh + (size_t)c0 * D) + lane);
        uint4 v1 = __ldg((const uint4*)(g_xh + (size_t)c1 * D) + lane);
        s += n0 + n1;
        acc_half8(a, v0, n0);
        acc_half8(a, v1, n1);
    }
    if (j < end) {
        int   c  = __ldg(&g_colidx[j]);
        float nc = __ldg(&g_norm[c]);
        s += nc;
        uint4 v = __ldg((const uint4*)(g_xh + (size_t)c * D) + lane);
        acc_half8(a, v, nc);
    }

    float ni = g_norm[i];
    float c2 = ni * ni;
    const float4* xi = (const float4*)(x + (size_t)i * D + 8 * lane);
    float4 s0 = __ldg(&xi[0]);
    float4 s1 = __ldg(&xi[1]);

    float y0 = fmaf(ni, a[0], c2 * s0.x), y1 = fmaf(ni, a[1], c2 * s0.y);
    float y2 = fmaf(ni, a[2], c2 * s0.z), y3 = fmaf(ni, a[3], c2 * s0.w);
    float y4 = fmaf(ni, a[4], c2 * s1.x), y5 = fmaf(ni, a[5], c2 * s1.y);
    float y6 = fmaf(ni, a[6], c2 * s1.z), y7 = fmaf(ni, a[7], c2 * s1.w);

    __half2 p0 = __floats2half2_rn(y0, y1);
    __half2 p1 = __floats2half2_rn(y2, y3);
    __half2 p2 = __floats2half2_rn(y4, y5);
    __half2 p3 = __floats2half2_rn(y6, y7);
    uint4 u;
    u.x = *(uint32_t*)&p0; u.y = *(uint32_t*)&p1;
    u.z = *(uint32_t*)&p2; u.w = *(uint32_t*)&p3;
    *(uint4*)(g_yh + (size_t)i * D + 8 * lane) = u;
    if (lane == 0) g_bcoef[i] = ni * (s + ni);
}

// ---------------- WMMA GEMM (single fp16 pass, K = 256) --------------------
#define GBM 128
#define GBN 128
#define GBK 32
#define NST 8
#define TS 40
#define TILE_BYTES (128 * TS * 2)
#define STG_LD 132
#define SMEM_BIAS 0
#define SMEM_TILES 512
#define GEMM_SMEM (512 + 128 * STG_LD * 4)

__global__ __launch_bounds__(256, 2) void k_gemm_wmma(const float* __restrict__ bias,
                                                      float* __restrict__ out, int M) {
    extern __shared__ char sm[];
    float* s_bias = (float*)(sm + SMEM_BIAS);
    char*  tiles  = sm + SMEM_TILES;
    __half* Abuf[2] = {(__half*)(tiles),                  (__half*)(tiles + 2 * TILE_BYTES)};
    __half* Bbuf[2] = {(__half*)(tiles + TILE_BYTES),     (__half*)(tiles + 3 * TILE_BYTES)};
    float* stg = (float*)tiles;

    int tid = threadIdx.x;
    int wid = tid >> 5;
    int wm  = wid & 3;
    int wn  = wid >> 2;
    int bn  = blockIdx.x * GBN;
    int bm  = blockIdx.y * GBM;

    if (tid < 128) s_bias[tid] = bias[bn + tid];

    wmma::fragment<wmma::accumulator, 16, 16, 16, float> acc[2][4];
#pragma unroll
    for (int i = 0; i < 2; i++)
#pragma unroll
        for (int jj = 0; jj < 4; jj++) wmma::fill_fragment(acc[i][jj], 0.f);

    auto issue = [&](int c) {
        int kk = c * GBK;
        __half* Ad = Abuf[c & 1];
        __half* Bd = Bbuf[c & 1];
#pragma unroll
        for (int r = 0; r < 2; r++) {
            int u   = tid + r * 256;
            int row = u >> 2;
            int c8  = (u & 3) * 8;
            cp16(Ad + row * TS + c8, g_yh + (size_t)(bm + row) * D + kk + c8);
            cp16(Bd + row * TS + c8, g_Wh + (size_t)(bn + row) * D + kk + c8);
        }
    };

    issue(0);
    CP_COMMIT();
    for (int c = 0; c < NST; c++) {
        if (c + 1 < NST) { issue(c + 1); CP_COMMIT(); CP_WAIT(1); }
        else             { CP_WAIT(0); }
        __syncthreads();

        const __half* As = Abuf[c & 1];
        const __half* Bs = Bbuf[c & 1];
#pragma unroll
        for (int ks = 0; ks < GBK; ks += 16) {
            wmma::fragment<wmma::matrix_a, 16, 16, 16, __half, wmma::row_major> af[2];
            wmma::fragment<wmma::matrix_b, 16, 16, 16, __half, wmma::col_major> bf[4];
#pragma unroll
            for (int i = 0; i < 2; i++)
                wmma::load_matrix_sync(af[i], As + (wm * 32 + i * 16) * TS + ks, TS);
#pragma unroll
            for (int jj = 0; jj < 4; jj++)
                wmma::load_matrix_sync(bf[jj], Bs + (wn * 64 + jj * 16) * TS + ks, TS);
#pragma unroll
            for (int i = 0; i < 2; i++)
#pragma unroll
                for (int jj = 0; jj < 4; jj++)
                    wmma::mma_sync(acc[i][jj], af[i], bf[jj], acc[i][jj]);
        }
        __syncthreads();
    }

#pragma unroll
    for (int i = 0; i < 2; i++)
#pragma unroll
        for (int jj = 0; jj < 4; jj++)
            wmma::store_matrix_sync(stg + (size_t)(wm * 32 + i * 16) * STG_LD + wn * 64 + jj * 16,
                                    acc[i][jj], STG_LD, wmma::mem_row_major);
    __syncthreads();

    int row  = tid >> 1;
    int half = tid & 1;
    int m    = bm + row;
    if (m < M) {
        float bc = g_bcoef[m];
        const float* sr = stg + (size_t)row * STG_LD + half * 64;
        float*       op = out + (size_t)m * D + bn + half * 64;
        const float* bl = s_bias + half * 64;
#pragma unroll
        for (int q = 0; q < 16; q++) {
            float4 v;
            v.x = sr[4 * q + 0] + bc * bl[4 * q + 0];
            v.y = sr[4 * q + 1] + bc * bl[4 * q + 1];
            v.z = sr[4 * q + 2] + bc * bl[4 * q + 2];
            v.w = sr[4 * q + 3] + bc * bl[4 * q + 3];
            *(float4*)(op + 4 * q) = v;
        }
    }
}

// ------------------------------------------------------------- entry point
extern "C" void kernel_launch(void* const* d_in, const int* in_sizes, int n_in,
                              void* d_out, int out_size) {
    const float* x    = (const float*)d_in[0];
    const float* W    = (const float*)d_in[1];
    const float* bias = (const float*)d_in[2];
    const int*   rows = (const int*)d_in[3];
    const int*   cols = (const int*)d_in[4];
    int N = in_sizes[0] / D;
    int E = in_sizes[3];
    if (N > NODES_MAX) N = NODES_MAX;
    if (E > EDGES_MAX) E = EDGES_MAX;

    cudaFuncSetAttribute(k_gemm_wmma, cudaFuncAttributeMaxDynamicSharedMemorySize, GEMM_SMEM);

    k_zero<<<(N + 255) / 256, 256>>>(N);
    k_hist<<<(E + 255) / 256, 256>>>(rows, E);
    k_xhalf<<<(N * D / 4 + 255) / 256, 256>>>(x, N * D / 4);
    k_whalf<<<(D * D + 255) / 256, 256>>>(W);
    k_part<<<SCAN_B, 1024>>>(N);
    k_top<<<1, 32>>>();
    k_down<<<SCAN_B, 1024>>>(N);
    k_scatter<<<(E + 255) / 256, 256>>>(rows, cols, E);
    k_aggregate<<<(N * 32 + 255) / 256, 256>>>(x, N);
    dim3 grid(D / GBN, (N + GBM - 1) / GBM);
    k_gemm_wmma<<<grid, 256, GEMM_SMEM>>>(bias, (float*)d_out, N);
}